// round 11
// baseline (speedup 1.0000x reference)
#include <cuda_runtime.h>
#include <cstdint>

#define RADIUS 5
#define RS 11
#define EMB 128
#define ROW_B (EMB * 4)            // 512 B per row
#define BB 32
#define LL 512
#define THREADS 256

// ---- register-path tile (round-8 kernel): positions [0, 256) per batch ----
#define CR 4                        // outputs per warp
#define TR (CR + 2 * RADIUS)        // 14 tokens per warp
#define REG_POS 256                 // positions handled by register path
#define REG_BLOCKS (BB * REG_POS / CR / 8)   // 256

// ---- DMA-path tile: positions [256, 512) per batch ----
#define CD 8                        // outputs per block (1 per warp)
#define TD (CD + 2 * RADIUS)        // 18 tokens per block
#define NROWS_D (CD * RS)           // 88 rows = 45056 B
#define DMA_BLOCKS (BB * (LL - REG_POS) / CD) // 1024
#define RING_OFF 512
#define SMEM_BYTES (RING_OFF + NROWS_D * ROW_B)  // 45568

#define GRID (REG_BLOCKS + DMA_BLOCKS)  // 1280, interleaved 1:4

// prefix sums of run lengths len(t)=min(11,t+1)-max(0,t-7), t=0..17 (sum 88)
__constant__ int PREF8[TD] =
    {0,1,3,6,10,15,21,28,36,44,52,60,67,73,78,82,85,87};

__device__ __forceinline__ uint32_t smem_u32(const void* p) {
    uint32_t a;
    asm("{ .reg .u64 t; cvta.to.shared.u64 t, %1; cvt.u32.u64 %0, t; }"
        : "=r"(a) : "l"(p));
    return a;
}
__device__ __forceinline__ void mbar_init(uint32_t a, uint32_t c) {
    asm volatile("mbarrier.init.shared.b64 [%0], %1;" :: "r"(a), "r"(c) : "memory");
}
__device__ __forceinline__ void mbar_expect_tx(uint32_t a, uint32_t bytes) {
    asm volatile("mbarrier.arrive.expect_tx.shared.b64 _, [%0], %1;"
                 :: "r"(a), "r"(bytes) : "memory");
}
__device__ __forceinline__ void mbar_wait(uint32_t a, uint32_t parity) {
    asm volatile(
        "{\n\t.reg .pred P;\n"
        "W_%=:\n\t"
        "mbarrier.try_wait.parity.acquire.cta.shared::cta.b64 P, [%0], %1, 0x989680;\n\t"
        "@P bra D_%=;\n\t"
        "bra W_%=;\n"
        "D_%=:\n\t}"
        :: "r"(a), "r"(parity) : "memory");
}
__device__ __forceinline__ void bulk_g2s(uint32_t dst, const void* src,
                                         uint32_t bytes, uint32_t mbar) {
    asm volatile(
        "cp.async.bulk.shared::cta.global.mbarrier::complete_tx::bytes "
        "[%0], [%1], %2, [%3];"
        :: "r"(dst), "l"(src), "r"(bytes), "r"(mbar) : "memory");
}

// Hybrid: the register-LDG path saturates the per-SM L1tex MSHR budget
// (~64 lines in flight -> ~31 B/cyc/SM, the 12.8us plateau) while the
// cp.async.bulk path pulls its share through the TMA/LTS queue, which does
// not consume MSHR entries. Interleaving 1 reg block per 4 DMA blocks puts
// both engines to work on every SM concurrently.
__global__ __launch_bounds__(THREADS) void region_encoder_kernel(
    const int* __restrict__ seq32,
    const float* __restrict__ W,
    const float* __restrict__ U,
    float* __restrict__ out)
{
    extern __shared__ __align__(128) unsigned char smem[];
    const int tid  = threadIdx.x;
    const int wid  = tid >> 5;
    const int lane = tid & 31;

    const int grp = blockIdx.x / 5;
    const int rem = blockIdx.x % 5;

    if (rem == 0) {
        // ================= register path: positions [0, 256) =================
        const int rb   = grp;                       // 0..255
        const int warp = rb * 8 + wid;              // 2048 warps
        const int b    = warp >> 6;                 // 64 warps per batch
        const int L0   = (warp & 63) * CR;          // in [0, 256)

        // dtype detect (lanes 16..31 sample odd words; int64 => all zero)
        int det = 0;
        if (lane >= 16) det = seq32[((lane - 16) << 1) + 1];
        const int p    = L0 - RADIUS + lane;
        const bool inb = (lane < TR) && ((unsigned)p < (unsigned)LL);
        const int idx  = b * LL + p;
        int tok = inb ? __ldg(seq32 + idx) : 0;
        const unsigned ball = __ballot_sync(0xffffffffu, det != 0);
        if (ball == 0u) tok = inb ? __ldg(seq32 + (idx << 1)) : 0;

        float4 w[CR]; float msk[CR]; float4 acc[CR];
#pragma unroll
        for (int i = 0; i < CR; i++) {
            const int ct = __shfl_sync(0xffffffffu, tok, i + RADIUS);
            w[i] = __ldg(reinterpret_cast<const float4*>(W + (size_t)ct * EMB) + lane);
            msk[i] = (ct != 0) ? 1.0f : 0.0f;
            acc[i] = make_float4(-INFINITY, -INFINITY, -INFINITY, -INFINITY);
        }

#pragma unroll
        for (int t = 0; t < TR; t++) {
            const int tk = __shfl_sync(0xffffffffu, tok, t);
            const float4* base =
                reinterpret_cast<const float4*>(U + (size_t)tk * RS * EMB);
#pragma unroll
            for (int j = 0; j < RS; j++) {
                const int i = t - j;
                if (i >= 0 && i < CR) {
                    const float4 u = __ldg(base + j * (EMB / 4) + lane);
                    acc[i].x = fmaxf(acc[i].x, u.x * w[i].x);
                    acc[i].y = fmaxf(acc[i].y, u.y * w[i].y);
                    acc[i].z = fmaxf(acc[i].z, u.z * w[i].z);
                    acc[i].w = fmaxf(acc[i].w, u.w * w[i].w);
                }
            }
        }

#pragma unroll
        for (int i = 0; i < CR; i++) {
            float4 h = make_float4(acc[i].x * msk[i], acc[i].y * msk[i],
                                   acc[i].z * msk[i], acc[i].w * msk[i]);
            __stcs(reinterpret_cast<float4*>(
                       out + (size_t)(b * LL + L0 + i) * EMB) + lane, h);
        }
    } else {
        // ================= DMA path: positions [256, 512) =================
        const int db = grp * 4 + (rem - 1);          // 0..1023
        const int b  = db >> 5;                      // 32 chunks per batch
        const int L0 = REG_POS + (db & 31) * CD;

        const uint32_t mb = smem_u32(smem);
        const uint32_t rg = mb + RING_OFF;
        if (tid == 0) mbar_init(mb, 1);
        __syncthreads();

        // window tokens: lane = t in [0, 18); lanes 18..31 dtype-detect
        int det = 0;
        if (lane >= TD) det = seq32[((lane - TD) << 1) + 1];
        const int p    = L0 - RADIUS + lane;
        const bool inb = (lane < TD) && ((unsigned)p < (unsigned)LL);
        const int idx  = b * LL + p;
        int tok = inb ? __ldg(seq32 + idx) : 0;
        const unsigned ball = __ballot_sync(0xffffffffu, det != 0);
        if (ball == 0u) tok = inb ? __ldg(seq32 + (idx << 1)) : 0;

        // warp 0 fires all 18 bulk copies (token t's exact row run)
        if (wid == 0) {
            if (lane == 0) mbar_expect_tx(mb, NROWS_D * ROW_B);
            __syncwarp();
            if (lane < TD) {
                const int t  = lane;
                const int lo = max(0, t - (CD - 1));
                const int hi = min(RS, t + 1);
                bulk_g2s(rg + (uint32_t)PREF8[t] * ROW_B,
                         (const char*)U + ((size_t)tok * RS + lo) * ROW_B,
                         (uint32_t)(hi - lo) * ROW_B, mb);
            }
        }

        // consumer: warp wid owns output i = wid (0..7)
        const int i  = wid;
        const int ct = __shfl_sync(0xffffffffu, tok, i + RADIUS);
        const float4 wv =
            __ldg(reinterpret_cast<const float4*>(W + (size_t)ct * EMB) + lane);
        const float m = (ct != 0) ? 1.0f : 0.0f;

        mbar_wait(mb, 0);

        float4 a = make_float4(-INFINITY, -INFINITY, -INFINITY, -INFINITY);
        const float4* rows = reinterpret_cast<const float4*>(smem + RING_OFF);
#pragma unroll
        for (int j = 0; j < RS; j++) {
            const int t = i + j;
            const int s = PREF8[t] + j - max(0, t - (CD - 1));
            const float4 u = rows[s * (EMB / 4) + lane];
            a.x = fmaxf(a.x, u.x * wv.x);
            a.y = fmaxf(a.y, u.y * wv.y);
            a.z = fmaxf(a.z, u.z * wv.z);
            a.w = fmaxf(a.w, u.w * wv.w);
        }

        float4 h = make_float4(a.x * m, a.y * m, a.z * m, a.w * m);
        __stcs(reinterpret_cast<float4*>(
                   out + (size_t)(b * LL + L0 + i) * EMB) + lane, h);
    }
}

extern "C" void kernel_launch(void* const* d_in, const int* in_sizes, int n_in,
                              void* d_out, int out_size) {
    const int*   seq32 = (const int*)d_in[0];
    const float* W     = (const float*)d_in[1];
    const float* U     = (const float*)d_in[2];
    float*       out   = (float*)d_out;

    cudaFuncSetAttribute(region_encoder_kernel,
                         cudaFuncAttributeMaxDynamicSharedMemorySize, SMEM_BYTES);

    region_encoder_kernel<<<GRID, THREADS, SMEM_BYTES>>>(seq32, W, U, out);
}

// round 13
// speedup vs baseline: 1.4147x; 1.4147x over previous
#include <cuda_runtime.h>
#include <cstdint>

#define RADIUS 5
#define RS 11
#define EMB 128
#define ROW_B (EMB * 4)            // 512 B per row
#define BB 32
#define LL 512
#define C_BLK 16                   // outputs per block (2 per warp)
#define T_BLK (C_BLK + 2*RADIUS)   // 26 tokens
#define NROWS_E 88                 // rows from even-t tokens -> smem (45056 B)
#define THREADS 256
#define RING_OFF 512
#define SMEM_BYTES (RING_OFF + NROWS_E * ROW_B)   // 45568

// prefix sums of run lengths len(t)=min(11,t+1)-max(0,t-15) over EVEN t=0,2,..,24
__constant__ int PREF_E[13] = {0,1,4,9,16,25,36,47,58,68,76,82,86};

__device__ __forceinline__ uint32_t smem_u32(const void* p) {
    uint32_t a;
    asm("{ .reg .u64 t; cvta.to.shared.u64 t, %1; cvt.u32.u64 %0, t; }"
        : "=r"(a) : "l"(p));
    return a;
}
__device__ __forceinline__ void mbar_init(uint32_t a, uint32_t c) {
    asm volatile("mbarrier.init.shared.b64 [%0], %1;" :: "r"(a), "r"(c) : "memory");
}
__device__ __forceinline__ void mbar_expect_tx(uint32_t a, uint32_t bytes) {
    asm volatile("mbarrier.arrive.expect_tx.shared.b64 _, [%0], %1;"
                 :: "r"(a), "r"(bytes) : "memory");
}
__device__ __forceinline__ void mbar_wait(uint32_t a, uint32_t parity) {
    asm volatile(
        "{\n\t.reg .pred P;\n"
        "W_%=:\n\t"
        "mbarrier.try_wait.parity.acquire.cta.shared::cta.b64 P, [%0], %1, 0x989680;\n\t"
        "@P bra D_%=;\n\t"
        "bra W_%=;\n"
        "D_%=:\n\t}"
        :: "r"(a), "r"(parity) : "memory");
}
__device__ __forceinline__ void bulk_g2s(uint32_t dst, const void* src,
                                         uint32_t bytes, uint32_t mbar) {
    asm volatile(
        "cp.async.bulk.shared::cta.global.mbarrier::complete_tx::bytes "
        "[%0], [%1], %2, [%3];"
        :: "r"(dst), "l"(src), "r"(bytes), "r"(mbar) : "memory");
}

// Intra-block hybrid: the LDG/MSHR path (plateaued at ~31 B/cyc/SM) and the
// cp.async.bulk/TMA path are separate request queues under the shared LTS
// cap. Even-t tokens' contiguous row-runs arrive via 13 bulk copies into
// smem; odd-t rows via 11 front-batched LDG.128 per warp. Both engines are
// in flight in EVERY block simultaneously.
// Round-12 bug fixed: the producer shuffle now uses a full member mask with
// all 32 lanes participating (reading lane 2*lane for lane<13); the old
// 0x1fff-mask shuffle read non-participating source lanes (UB -> garbage).
__global__ __launch_bounds__(THREADS, 3) void region_encoder_kernel(
    const int* __restrict__ seq32,
    const float* __restrict__ W,
    const float* __restrict__ U,
    float* __restrict__ out)
{
    extern __shared__ __align__(128) unsigned char smem[];
    const int tid  = threadIdx.x;
    const int wid  = tid >> 5;
    const int lane = tid & 31;
    const int b    = blockIdx.x >> 5;            // batch
    const int L0   = (blockIdx.x & 31) * C_BLK;  // first output of chunk

    const uint32_t mb = smem_u32(smem);
    const uint32_t rg = mb + RING_OFF;
    if (tid == 0) mbar_init(mb, 1);
    __syncthreads();

    // ---- window tokens (lane = t in [0,26)) + dtype detection ----
    // Lanes 26..31 sample odd 32-bit words of seq: int64 layout => all zero;
    // int32 layout (tokens uniform in [0,50000)) => essentially never all zero.
    int det = 0;
    if (lane >= T_BLK) det = seq32[((lane - T_BLK) << 1) + 1];
    const int p    = L0 - RADIUS + lane;
    const bool inb = (lane < T_BLK) && ((unsigned)p < (unsigned)LL);
    const int idx  = b * LL + p;
    int tok = inb ? __ldg(seq32 + idx) : 0;
    const unsigned ball = __ballot_sync(0xffffffffu, det != 0);
    if (ball == 0u) tok = inb ? __ldg(seq32 + (idx << 1)) : 0;  // int64 layout

    // ---- warp 0: fire 13 bulk copies (even tokens' runs) FIRST ----
    if (wid == 0) {
        if (lane == 0) mbar_expect_tx(mb, NROWS_E * ROW_B);
        __syncwarp();
        // FULL-mask shuffle: every lane participates; lane<13 selects source 2*lane.
        const int t   = (lane < 13) ? (lane * 2) : 0;
        const int tk  = __shfl_sync(0xffffffffu, tok, t);
        if (lane < 13) {
            const int lo = max(0, t - (C_BLK - 1));
            const int hi = min(RS, t + 1);
            bulk_g2s(rg + (uint32_t)PREF_E[lane] * ROW_B,
                     (const char*)U + ((size_t)tk * RS + lo) * ROW_B,
                     (uint32_t)(hi - lo) * ROW_B, mb);
        }
    }

    // ---- every warp: outputs i0 = 2*wid (even), i0+1 ----
    const int i0 = wid * 2;

    // odd-t rows via front-batched LDG.128: for each j, the odd t of the pair
    // {i0+j, i0+1+j} is i0 + j + ((j&1) ? 0 : 1)   (i0 even => parity = j&1)
    float4 uo[RS];
#pragma unroll
    for (int j = 0; j < RS; j++) {
        const int t_odd = i0 + j + ((j & 1) ? 0 : 1);
        const int tk = __shfl_sync(0xffffffffu, tok, t_odd);
        uo[j] = __ldg(reinterpret_cast<const float4*>(
                          U + ((size_t)tk * RS + j) * EMB) + lane);
    }

    const int c0 = __shfl_sync(0xffffffffu, tok, i0 + RADIUS);
    const int c1 = __shfl_sync(0xffffffffu, tok, i0 + 1 + RADIUS);
    const float4 w0 = __ldg(reinterpret_cast<const float4*>(W + (size_t)c0 * EMB) + lane);
    const float4 w1 = __ldg(reinterpret_cast<const float4*>(W + (size_t)c1 * EMB) + lane);
    const float  m0 = (c0 != 0) ? 1.0f : 0.0f;
    const float  m1 = (c1 != 0) ? 1.0f : 0.0f;

    mbar_wait(mb, 0);

    float4 a0 = make_float4(-INFINITY, -INFINITY, -INFINITY, -INFINITY);
    float4 a1 = a0;
    const float4* rows = reinterpret_cast<const float4*>(smem + RING_OFF);
#pragma unroll
    for (int j = 0; j < RS; j++) {
        // even t of the pair -> smem; odd t -> uo[j]
        const int t_even = i0 + j + ((j & 1) ? 1 : 0);
        const int s = PREF_E[t_even >> 1] + (j - max(0, t_even - (C_BLK - 1)));
        const float4 ue = rows[s * (EMB / 4) + lane];
        const float4 ur = uo[j];
        if ((j & 1) == 0) {
            // j even: t0 = i0+j even (smem -> out0), t1 odd (reg -> out1)
            a0.x = fmaxf(a0.x, ue.x * w0.x);  a1.x = fmaxf(a1.x, ur.x * w1.x);
            a0.y = fmaxf(a0.y, ue.y * w0.y);  a1.y = fmaxf(a1.y, ur.y * w1.y);
            a0.z = fmaxf(a0.z, ue.z * w0.z);  a1.z = fmaxf(a1.z, ur.z * w1.z);
            a0.w = fmaxf(a0.w, ue.w * w0.w);  a1.w = fmaxf(a1.w, ur.w * w1.w);
        } else {
            // j odd: t0 = i0+j odd (reg -> out0), t1 even (smem -> out1)
            a0.x = fmaxf(a0.x, ur.x * w0.x);  a1.x = fmaxf(a1.x, ue.x * w1.x);
            a0.y = fmaxf(a0.y, ur.y * w0.y);  a1.y = fmaxf(a1.y, ue.y * w1.y);
            a0.z = fmaxf(a0.z, ur.z * w0.z);  a1.z = fmaxf(a1.z, ue.z * w1.z);
            a0.w = fmaxf(a0.w, ur.w * w0.w);  a1.w = fmaxf(a1.w, ue.w * w1.w);
        }
    }

    float4 h0 = make_float4(a0.x * m0, a0.y * m0, a0.z * m0, a0.w * m0);
    float4 h1 = make_float4(a1.x * m1, a1.y * m1, a1.z * m1, a1.w * m1);
    __stcs(reinterpret_cast<float4*>(out + (size_t)(b * LL + L0 + i0)     * EMB) + lane, h0);
    __stcs(reinterpret_cast<float4*>(out + (size_t)(b * LL + L0 + i0 + 1) * EMB) + lane, h1);
}

extern "C" void kernel_launch(void* const* d_in, const int* in_sizes, int n_in,
                              void* d_out, int out_size) {
    const int*   seq32 = (const int*)d_in[0];
    const float* W     = (const float*)d_in[1];
    const float* U     = (const float*)d_in[2];
    float*       out   = (float*)d_out;

    cudaFuncSetAttribute(region_encoder_kernel,
                         cudaFuncAttributeMaxDynamicSharedMemorySize, SMEM_BYTES);

    const int blocks = BB * (LL / C_BLK);  // 1024
    region_encoder_kernel<<<blocks, THREADS, SMEM_BYTES>>>(seq32, W, U, out);
}